// round 16
// baseline (speedup 1.0000x reference)
#include <cuda_runtime.h>
#include <cuda_fp16.h>
#include <cstdint>
#include <cstddef>

// ----------------------------------------------------------------------------
// Problem constants
// ----------------------------------------------------------------------------
#define KDIM   12288
#define BROWS  8192
#define CCOLS  1000
#define CPAD   1024

#define TILE_M 128
#define TILE_N 256                         // fatter tile: warp 64x64
#define KBLK   128                         // fp8 elements per k-block (128 B/row)
#define STAGES 3
#define NSPLIT 4
#define KSPLIT (KDIM / NSPLIT)             // 3072
#define NIT    (KSPLIT / KBLK)             // 24 iterations per work unit

// rows pitched to 144B -> 16B-chunk bank-group (9r + c) % 8 == (r + c) % 8,
// bijective over 8 consecutive rows => conflict-free ldmatrix AND cp.async.
#define ROW_PITCH     144
#define STAGE_ROWS    (TILE_M + TILE_N)               // 384
#define STAGE_BYTES   (STAGE_ROWS * ROW_PITCH)        // 55296
#define SMEM_DYN      (STAGES * STAGE_BYTES)          // 165888 (occ 1)

// e4m3 constants:  +1 = 0x38, -1 = 0xB8, 0 = 0x00
#define FP8_P1 0x38u
#define FP8_N1 0xB8u

// ----------------------------------------------------------------------------
// Scratch (no cudaMalloc allowed)
// ----------------------------------------------------------------------------
__device__ uint8_t g_A[(size_t)BROWS * KDIM];             // 100.7 MB e4m3 sign(x)
__device__ uint8_t g_W[(size_t)CPAD  * KDIM];             // 12.6 MB e4m3 sign(w)
__device__ __half  g_P[(size_t)NSPLIT * BROWS * CPAD];    // 67 MB f16 partials

// ----------------------------------------------------------------------------
// Helpers
// ----------------------------------------------------------------------------
__device__ __forceinline__ uint32_t smem_u32(const void* p) {
    uint32_t a;
    asm("{ .reg .u64 t; cvta.to.shared.u64 t, %1; cvt.u32.u64 %0, t; }" : "=r"(a) : "l"(p));
    return a;
}
__device__ __forceinline__ void cpa16(uint32_t dst, const void* src) {
    asm volatile("cp.async.cg.shared.global [%0], [%1], 16;" :: "r"(dst), "l"(src) : "memory");
}
__device__ __forceinline__ void cpa_commit() {
    asm volatile("cp.async.commit_group;" ::: "memory");
}
template <int N>
__device__ __forceinline__ void cpa_wait() {
    asm volatile("cp.async.wait_group %0;" :: "n"(N) : "memory");
}
__device__ __forceinline__ void ldm_x4(uint32_t* r, uint32_t addr) {
    asm volatile("ldmatrix.sync.aligned.m8n8.x4.shared.b16 {%0,%1,%2,%3}, [%4];"
                 : "=r"(r[0]), "=r"(r[1]), "=r"(r[2]), "=r"(r[3]) : "r"(addr));
}
// fp8 e4m3 MMA with f16 accumulator. Exact here: every k32 contribution is an
// even integer and per-split |acc| <= 3072 < 4096 (even ints exact in f16).
__device__ __forceinline__ void mma_fp8h(uint32_t* c, const uint32_t* a,
                                         uint32_t b0, uint32_t b1) {
    asm volatile("mma.sync.aligned.m16n8k32.row.col.f16.e4m3.e4m3.f16 "
                 "{%0,%1}, {%2,%3,%4,%5}, {%6,%7}, {%0,%1};"
                 : "+r"(c[0]), "+r"(c[1])
                 : "r"(a[0]), "r"(a[1]), "r"(a[2]), "r"(a[3]), "r"(b0), "r"(b1));
}

// ----------------------------------------------------------------------------
// Phase 1: binarize fp32 -> e4m3 {-1, 0, +1}
// ----------------------------------------------------------------------------
__device__ __forceinline__ uint32_t sgn4f8(float4 f) {
    uint32_t b0 = (f.x == 0.0f) ? 0u : ((__float_as_uint(f.x) >> 31) ? FP8_N1 : FP8_P1);
    uint32_t b1 = (f.y == 0.0f) ? 0u : ((__float_as_uint(f.y) >> 31) ? FP8_N1 : FP8_P1);
    uint32_t b2 = (f.z == 0.0f) ? 0u : ((__float_as_uint(f.z) >> 31) ? FP8_N1 : FP8_P1);
    uint32_t b3 = (f.w == 0.0f) ? 0u : ((__float_as_uint(f.w) >> 31) ? FP8_N1 : FP8_P1);
    return b0 | (b1 << 8) | (b2 << 16) | (b3 << 24);
}

__global__ void __launch_bounds__(256) bin_input(const float* __restrict__ x) {
    size_t i4 = (size_t)blockIdx.x * blockDim.x + threadIdx.x;   // exact grid
    ((uint32_t*)g_A)[i4] = sgn4f8(((const float4*)x)[i4]);
}

__global__ void __launch_bounds__(256) bin_weight(const float* __restrict__ w) {
    size_t i4 = (size_t)blockIdx.x * blockDim.x + threadIdx.x;
    uint32_t v;
    if (i4 * 4 >= (size_t)CCOLS * KDIM) v = FP8_P1 * 0x01010101u;  // pad (discarded)
    else                                v = sgn4f8(((const float4*)w)[i4]);
    ((uint32_t*)g_W)[i4] = v;
}

// ----------------------------------------------------------------------------
// Phase 2: fp8 mma.sync (f16 acc) GEMM, split-K=4, CTA 128x256x3072,
//          warp tile 64x64 (2M x 4N), occ 1, double-buffered fragments.
// smem traffic: A read 4x + B read 2x = 176KB/iter for 2x output vs old 128KB
// ----------------------------------------------------------------------------
__global__ void __launch_bounds__(256, 1) bgemm(void) {
    extern __shared__ __align__(128) char dynsmem[];
    const uint32_t dynb = smem_u32(dynsmem);

    const int tid  = threadIdx.x;
    const int wid  = tid >> 5;
    const int lane = tid & 31;
    const int wm   = wid & 1;                  // 2 M-warps (64 rows)
    const int wn   = wid >> 1;                 // 4 N-warps (64 cols)

    const int ntile = blockIdx.x & 3;          // 4 N-tiles of 256
    const int mtile = (blockIdx.x >> 2) & 63;
    const int split = blockIdx.x >> 8;         // 0..3
    const int mbase = mtile * TILE_M;
    const int nbase = ntile * TILE_N;
    const size_t kofs = (size_t)split * KSPLIT;

    // --- producer: 12 chunks/thread (4 A rows + 8 B rows, stride 32)
    const int r0 = tid >> 3;                   // 0..31
    const int ch = tid & 7;                    // 16B chunk within 128B row
    const uint8_t* gA = g_A + (size_t)(mbase + r0) * KDIM + kofs + ch * 16;
    const uint8_t* gB = g_W + (size_t)(nbase + r0) * KDIM + kofs + ch * 16;
    const uint32_t sA = (uint32_t)(r0 * ROW_PITCH + ch * 16);
    const size_t rstep = (size_t)32 * KDIM;

    // per-lane ldmatrix offsets: (lane&15) row, (lane&16) 16B half of k32 step
    const uint32_t a_off = (uint32_t)(wm * 64 + (lane & 15)) * ROW_PITCH + (lane & 16);
    const uint32_t b_off = (uint32_t)(TILE_M + wn * 64 + (lane & 15)) * ROW_PITCH + (lane & 16);

    uint32_t acc[4][8][2];                     // f16x2 accumulators (64 regs)
    #pragma unroll
    for (int f = 0; f < 4; ++f)
        #pragma unroll
        for (int q = 0; q < 8; ++q) { acc[f][q][0] = 0u; acc[f][q][1] = 0u; }

    // prologue: fill STAGES-1 stages
    #pragma unroll
    for (int p = 0; p < STAGES - 1; ++p) {
        const uint32_t sb = dynb + p * STAGE_BYTES;
        const size_t kb = (size_t)p * KBLK;
        #pragma unroll
        for (int j = 0; j < 4; ++j)
            cpa16(sb + sA + (j * 32) * ROW_PITCH, gA + j * rstep + kb);
        #pragma unroll
        for (int j = 0; j < 8; ++j)
            cpa16(sb + sA + (TILE_M + j * 32) * ROW_PITCH, gB + j * rstep + kb);
        cpa_commit();
    }

    int sc = 0, sp = STAGES - 1;               // consumer / producer stage idx
    #pragma unroll 1
    for (int it = 0; it < NIT; ++it) {
        cpa_wait<STAGES - 2>();
        __syncthreads();

        if (it + STAGES - 1 < NIT) {
            const uint32_t sb = dynb + sp * STAGE_BYTES;
            const size_t kb = (size_t)(it + STAGES - 1) * KBLK;
            #pragma unroll
            for (int j = 0; j < 4; ++j)
                cpa16(sb + sA + (j * 32) * ROW_PITCH, gA + j * rstep + kb);
            #pragma unroll
            for (int j = 0; j < 8; ++j)
                cpa16(sb + sA + (TILE_M + j * 32) * ROW_PITCH, gB + j * rstep + kb);
        }
        cpa_commit();
        if (++sp == STAGES) sp = 0;

        const uint32_t sbase = dynb + sc * STAGE_BYTES;
        if (++sc == STAGES) sc = 0;

        // double-buffered fragment pipeline over four k32 steps
        uint32_t ar[2][4][4], br[2][4][4];
        #pragma unroll
        for (int f = 0; f < 4; ++f)
            ldm_x4(ar[0][f], sbase + a_off + f * 16 * ROW_PITCH);
        #pragma unroll
        for (int p = 0; p < 4; ++p)
            ldm_x4(br[0][p], sbase + b_off + p * 16 * ROW_PITCH);

        #pragma unroll
        for (int s = 0; s < 4; ++s) {
            const int cur = s & 1, nxt = cur ^ 1;
            if (s < 3) {                       // prefetch next step's fragments
                #pragma unroll
                for (int f = 0; f < 4; ++f)
                    ldm_x4(ar[nxt][f], sbase + a_off + f * 16 * ROW_PITCH + (s + 1) * 32);
                #pragma unroll
                for (int p = 0; p < 4; ++p)
                    ldm_x4(br[nxt][p], sbase + b_off + p * 16 * ROW_PITCH + (s + 1) * 32);
            }
            #pragma unroll
            for (int f = 0; f < 4; ++f)
                #pragma unroll
                for (int q = 0; q < 8; ++q)
                    mma_fp8h(acc[f][q], ar[cur][f],
                             br[cur][q >> 1][q & 1], br[cur][q >> 1][2 + (q & 1)]);
        }
    }

    // epilogue: store f16x2 partials directly (no conversion)
    __half* pbase = g_P + (size_t)split * BROWS * CPAD;
    #pragma unroll
    for (int f = 0; f < 4; ++f) {
        const int m0 = mbase + wm * 64 + f * 16 + (lane >> 2);
        __half* r0o = pbase + (size_t)m0 * CPAD;
        __half* r1o = r0o + (size_t)8 * CPAD;
        #pragma unroll
        for (int q = 0; q < 8; ++q) {
            const int c = nbase + wn * 64 + q * 8 + 2 * (lane & 3);
            *(uint32_t*)(r0o + c) = acc[f][q][0];
            *(uint32_t*)(r1o + c) = acc[f][q][1];
        }
    }
}

// ----------------------------------------------------------------------------
// Phase 3: reduce 4 f16 partials -> out [8192 x 1000] (exact integer adds)
// ----------------------------------------------------------------------------
// thread handles 2 cols (one half2 per split); grid exact: 8192*500/256 = 16000
__global__ void __launch_bounds__(256) kreduce(float* __restrict__ out) {
    const size_t t   = (size_t)blockIdx.x * blockDim.x + threadIdx.x;
    const size_t row = t / 500;
    const int    c   = (int)(t % 500) * 2;
    const size_t pidx = row * CPAD + c;
    const size_t SP = (size_t)BROWS * CPAD;

    float2 a = __half22float2(*(const __half2*)(g_P + pidx));
    float2 b = __half22float2(*(const __half2*)(g_P + SP + pidx));
    float2 d = __half22float2(*(const __half2*)(g_P + 2 * SP + pidx));
    float2 e = __half22float2(*(const __half2*)(g_P + 3 * SP + pidx));
    float2 r;
    r.x = (a.x + b.x) + (d.x + e.x);
    r.y = (a.y + b.y) + (d.y + e.y);
    *(float2*)(out + row * CCOLS + c) = r;
}

// ----------------------------------------------------------------------------
// Launch
// ----------------------------------------------------------------------------
extern "C" void kernel_launch(void* const* d_in, const int* in_sizes, int n_in,
                              void* d_out, int out_size) {
    const float* x = (const float*)d_in[0];   // [8192, 12288] fp32
    const float* w = (const float*)d_in[1];   // [1000, 12288] fp32
    float* out = (float*)d_out;               // [8192, 1000] fp32
    (void)in_sizes; (void)n_in; (void)out_size;

    bin_input <<<(BROWS * (KDIM / 4)) / 256, 256>>>(x);
    bin_weight<<<(CPAD  * (KDIM / 4)) / 256, 256>>>(w);

    cudaFuncSetAttribute(bgemm, cudaFuncAttributeMaxDynamicSharedMemorySize, SMEM_DYN);
    bgemm<<<NSPLIT * (BROWS / TILE_M) * (CPAD / TILE_N), 256, SMEM_DYN>>>();

    kreduce<<<(BROWS * 500) / 256, 256>>>(out);   // 16000 blocks exact
}

// round 17
// speedup vs baseline: 1.0770x; 1.0770x over previous
#include <cuda_runtime.h>
#include <cuda_fp16.h>
#include <cstdint>
#include <cstddef>

// ----------------------------------------------------------------------------
// Problem constants
// ----------------------------------------------------------------------------
#define KDIM   12288
#define BROWS  8192
#define CCOLS  1000
#define CPAD   1024

#define TILE_M 128
#define TILE_N 128
#define KBLK   128                         // fp8 elements per k-block (128 B/row)
#define STAGES 3
#define NSPLIT 4
#define KSPLIT (KDIM / NSPLIT)             // 3072
#define NIT    (KSPLIT / KBLK)             // 24 iterations per work unit

// rows pitched to 144B -> 16B-chunk bank-group (9r + c) % 8 == (r + c) % 8,
// bijective over 8 consecutive rows => conflict-free ldmatrix AND cp.async.
#define ROW_PITCH     144
#define STAGE_ROWS    (TILE_M + TILE_N)               // 256
#define STAGE_BYTES   (STAGE_ROWS * ROW_PITCH)        // 36864
#define SMEM_DYN      (STAGES * STAGE_BYTES)          // 110592 (occ 2)

// e4m3 constants:  +1 = 0x38, -1 = 0xB8, 0 = 0x00
#define FP8_P1 0x38u
#define FP8_N1 0xB8u

// binarize grid split (exact):
#define ABLK 49152                         // 8192*12288/8/256
#define WBLK 6144                          // 1024*12288/8/256

// ----------------------------------------------------------------------------
// Scratch (no cudaMalloc allowed)
// ----------------------------------------------------------------------------
__device__ uint8_t g_A[(size_t)BROWS * KDIM];             // 100.7 MB e4m3 sign(x)
__device__ uint8_t g_W[(size_t)CPAD  * KDIM];             // 12.6 MB e4m3 sign(w)
__device__ __half  g_P[(size_t)NSPLIT * BROWS * CPAD];    // 67 MB f16 partials

// ----------------------------------------------------------------------------
// Helpers
// ----------------------------------------------------------------------------
__device__ __forceinline__ uint32_t smem_u32(const void* p) {
    uint32_t a;
    asm("{ .reg .u64 t; cvta.to.shared.u64 t, %1; cvt.u32.u64 %0, t; }" : "=r"(a) : "l"(p));
    return a;
}
__device__ __forceinline__ void cpa16(uint32_t dst, const void* src) {
    asm volatile("cp.async.cg.shared.global [%0], [%1], 16;" :: "r"(dst), "l"(src) : "memory");
}
__device__ __forceinline__ void cpa_commit() {
    asm volatile("cp.async.commit_group;" ::: "memory");
}
template <int N>
__device__ __forceinline__ void cpa_wait() {
    asm volatile("cp.async.wait_group %0;" :: "n"(N) : "memory");
}
__device__ __forceinline__ void ldm_x4(uint32_t* r, uint32_t addr) {
    asm volatile("ldmatrix.sync.aligned.m8n8.x4.shared.b16 {%0,%1,%2,%3}, [%4];"
                 : "=r"(r[0]), "=r"(r[1]), "=r"(r[2]), "=r"(r[3]) : "r"(addr));
}
// fp8 e4m3 MMA with f16 accumulator. Exact here: every k32 contribution is an
// even integer and per-split |acc| <= 3072 < 4096 (even ints exact in f16).
__device__ __forceinline__ void mma_fp8h(uint32_t* c, const uint32_t* a,
                                         uint32_t b0, uint32_t b1) {
    asm volatile("mma.sync.aligned.m16n8k32.row.col.f16.e4m3.e4m3.f16 "
                 "{%0,%1}, {%2,%3,%4,%5}, {%6,%7}, {%0,%1};"
                 : "+r"(c[0]), "+r"(c[1])
                 : "r"(a[0]), "r"(a[1]), "r"(a[2]), "r"(a[3]), "r"(b0), "r"(b1));
}

// ----------------------------------------------------------------------------
// Phase 1: binarize fp32 -> e4m3 {-1, 0, +1}; single merged kernel,
//          32 B/thread (MLP 2), streaming loads, 8 B packed stores.
// ----------------------------------------------------------------------------
__device__ __forceinline__ uint32_t sgn4f8(float4 f) {
    uint32_t b0 = (f.x == 0.0f) ? 0u : ((__float_as_uint(f.x) >> 31) ? FP8_N1 : FP8_P1);
    uint32_t b1 = (f.y == 0.0f) ? 0u : ((__float_as_uint(f.y) >> 31) ? FP8_N1 : FP8_P1);
    uint32_t b2 = (f.z == 0.0f) ? 0u : ((__float_as_uint(f.z) >> 31) ? FP8_N1 : FP8_P1);
    uint32_t b3 = (f.w == 0.0f) ? 0u : ((__float_as_uint(f.w) >> 31) ? FP8_N1 : FP8_P1);
    return b0 | (b1 << 8) | (b2 << 16) | (b3 << 24);
}

__global__ void __launch_bounds__(256) binarize(const float* __restrict__ x,
                                                const float* __restrict__ w) {
    const int bid = blockIdx.x;
    if (bid < ABLK) {
        const size_t i8 = (size_t)bid * 256 + threadIdx.x;   // uint2 index
        float4 f0 = __ldcs((const float4*)x + 2 * i8);
        float4 f1 = __ldcs((const float4*)x + 2 * i8 + 1);
        uint2 v;
        v.x = sgn4f8(f0);
        v.y = sgn4f8(f1);
        ((uint2*)g_A)[i8] = v;
    } else {
        const size_t i8 = (size_t)(bid - ABLK) * 256 + threadIdx.x;
        uint2 v;
        if (i8 * 8 >= (size_t)CCOLS * KDIM) {
            v.x = FP8_P1 * 0x01010101u;                      // pad rows (discarded)
            v.y = FP8_P1 * 0x01010101u;
        } else {
            float4 f0 = __ldcs((const float4*)w + 2 * i8);
            float4 f1 = __ldcs((const float4*)w + 2 * i8 + 1);
            v.x = sgn4f8(f0);
            v.y = sgn4f8(f1);
        }
        ((uint2*)g_W)[i8] = v;
    }
}

// ----------------------------------------------------------------------------
// Phase 2: fp8 mma.sync (f16 acc) GEMM, split-K=4, CTA unit 128x128x3072,
//          occ 2, double-buffered register fragments (best measured: R14).
// ----------------------------------------------------------------------------
__global__ void __launch_bounds__(256, 2) bgemm(void) {
    extern __shared__ __align__(128) char dynsmem[];
    const uint32_t dynb = smem_u32(dynsmem);

    const int tid  = threadIdx.x;
    const int wid  = tid >> 5;
    const int lane = tid & 31;
    const int wm   = wid & 3;                  // 4 M-warps (32 rows)
    const int wn   = wid >> 2;                 // 2 N-warps (64 cols)

    const int ntile = blockIdx.x & 7;
    const int mtile = (blockIdx.x >> 3) & 63;
    const int split = blockIdx.x >> 9;         // 0..3
    const int mbase = mtile * TILE_M;
    const int nbase = ntile * TILE_N;
    const size_t kofs = (size_t)split * KSPLIT;

    // --- producer addressing: 8 chunks/thread (4 A rows + 4 B rows, stride 32)
    const int r0 = tid >> 3;                   // 0..31
    const int ch = tid & 7;                    // 16B chunk within 128B row
    const uint8_t* gA = g_A + (size_t)(mbase + r0) * KDIM + kofs + ch * 16;
    const uint8_t* gB = g_W + (size_t)(nbase + r0) * KDIM + kofs + ch * 16;
    const uint32_t sA = (uint32_t)(r0 * ROW_PITCH + ch * 16);
    const size_t rstep = (size_t)32 * KDIM;

    // per-lane ldmatrix offsets: (lane&15) row, (lane&16) 16B half of k32 step
    const uint32_t a_off = (uint32_t)(wm * 32 + (lane & 15)) * ROW_PITCH + (lane & 16);
    const uint32_t b_off = (uint32_t)(TILE_M + wn * 64 + (lane & 15)) * ROW_PITCH + (lane & 16);

    uint32_t acc[2][8][2];                     // f16x2 accumulators (32 regs)
    #pragma unroll
    for (int f = 0; f < 2; ++f)
        #pragma unroll
        for (int q = 0; q < 8; ++q) { acc[f][q][0] = 0u; acc[f][q][1] = 0u; }

    // prologue: fill STAGES-1 stages
    #pragma unroll
    for (int p = 0; p < STAGES - 1; ++p) {
        const uint32_t sb = dynb + p * STAGE_BYTES;
        const size_t kb = (size_t)p * KBLK;
        #pragma unroll
        for (int j = 0; j < 4; ++j) {
            cpa16(sb + sA + (j * 32) * ROW_PITCH,            gA + j * rstep + kb);
            cpa16(sb + sA + (TILE_M + j * 32) * ROW_PITCH,   gB + j * rstep + kb);
        }
        cpa_commit();
    }

    int sc = 0, sp = STAGES - 1;               // consumer / producer stage idx
    #pragma unroll 1
    for (int it = 0; it < NIT; ++it) {
        cpa_wait<STAGES - 2>();
        __syncthreads();

        if (it + STAGES - 1 < NIT) {
            const uint32_t sb = dynb + sp * STAGE_BYTES;
            const size_t kb = (size_t)(it + STAGES - 1) * KBLK;
            #pragma unroll
            for (int j = 0; j < 4; ++j) {
                cpa16(sb + sA + (j * 32) * ROW_PITCH,          gA + j * rstep + kb);
                cpa16(sb + sA + (TILE_M + j * 32) * ROW_PITCH, gB + j * rstep + kb);
            }
        }
        cpa_commit();
        if (++sp == STAGES) sp = 0;

        const uint32_t sbase = dynb + sc * STAGE_BYTES;
        if (++sc == STAGES) sc = 0;

        // double-buffered fragment pipeline over four k32 steps
        uint32_t ar[2][2][4], br[2][4][4];
        ldm_x4(ar[0][0], sbase + a_off);
        ldm_x4(ar[0][1], sbase + a_off + 16 * ROW_PITCH);
        #pragma unroll
        for (int p = 0; p < 4; ++p)
            ldm_x4(br[0][p], sbase + b_off + p * 16 * ROW_PITCH);

        #pragma unroll
        for (int s = 0; s < 4; ++s) {
            const int cur = s & 1, nxt = cur ^ 1;
            if (s < 3) {                       // prefetch next step's fragments
                ldm_x4(ar[nxt][0], sbase + a_off + (s + 1) * 32);
                ldm_x4(ar[nxt][1], sbase + a_off + 16 * ROW_PITCH + (s + 1) * 32);
                #pragma unroll
                for (int p = 0; p < 4; ++p)
                    ldm_x4(br[nxt][p], sbase + b_off + p * 16 * ROW_PITCH + (s + 1) * 32);
            }
            #pragma unroll
            for (int f = 0; f < 2; ++f)
                #pragma unroll
                for (int q = 0; q < 8; ++q)
                    mma_fp8h(acc[f][q], ar[cur][f],
                             br[cur][q >> 1][q & 1], br[cur][q >> 1][2 + (q & 1)]);
        }
    }

    // epilogue: store f16x2 partials directly (no f32 conversion, half traffic)
    __half* pbase = g_P + (size_t)split * BROWS * CPAD;
    #pragma unroll
    for (int f = 0; f < 2; ++f) {
        const int m0 = mbase + wm * 32 + f * 16 + (lane >> 2);
        __half* r0o = pbase + (size_t)m0 * CPAD;
        __half* r1o = r0o + (size_t)8 * CPAD;
        #pragma unroll
        for (int q = 0; q < 8; ++q) {
            const int c = nbase + wn * 64 + q * 8 + 2 * (lane & 3);
            *(uint32_t*)(r0o + c) = acc[f][q][0];
            *(uint32_t*)(r1o + c) = acc[f][q][1];
        }
    }
}

// ----------------------------------------------------------------------------
// Phase 3: reduce 4 f16 partials -> out [8192 x 1000] (exact integer adds)
// ----------------------------------------------------------------------------
// thread handles 2 cols (one half2 per split); grid exact: 8192*500/256 = 16000
__global__ void __launch_bounds__(256) kreduce(float* __restrict__ out) {
    const size_t t   = (size_t)blockIdx.x * blockDim.x + threadIdx.x;
    const size_t row = t / 500;
    const int    c   = (int)(t % 500) * 2;
    const size_t pidx = row * CPAD + c;
    const size_t SP = (size_t)BROWS * CPAD;

    float2 a = __half22float2(*(const __half2*)(g_P + pidx));
    float2 b = __half22float2(*(const __half2*)(g_P + SP + pidx));
    float2 d = __half22float2(*(const __half2*)(g_P + 2 * SP + pidx));
    float2 e = __half22float2(*(const __half2*)(g_P + 3 * SP + pidx));
    float2 r;
    r.x = (a.x + b.x) + (d.x + e.x);
    r.y = (a.y + b.y) + (d.y + e.y);
    *(float2*)(out + row * CCOLS + c) = r;
}

// ----------------------------------------------------------------------------
// Launch
// ----------------------------------------------------------------------------
extern "C" void kernel_launch(void* const* d_in, const int* in_sizes, int n_in,
                              void* d_out, int out_size) {
    const float* x = (const float*)d_in[0];   // [8192, 12288] fp32
    const float* w = (const float*)d_in[1];   // [1000, 12288] fp32
    float* out = (float*)d_out;               // [8192, 1000] fp32
    (void)in_sizes; (void)n_in; (void)out_size;

    binarize<<<ABLK + WBLK, 256>>>(x, w);

    cudaFuncSetAttribute(bgemm, cudaFuncAttributeMaxDynamicSharedMemorySize, SMEM_DYN);
    bgemm<<<NSPLIT * (BROWS / TILE_M) * (CPAD / TILE_N), 256, SMEM_DYN>>>();

    kreduce<<<(BROWS * 500) / 256, 256>>>(out);   // 16000 blocks exact
}